// round 11
// baseline (speedup 1.0000x reference)
#include <cuda_runtime.h>
#include <cuda_bf16.h>

#define FEAT   24
#define NPIX   (FEAT*FEAT)        // 576
#define KANCH  9
#define NN     (NPIX*KANCH)       // 5184
#define MIDCH  24
#define CINCH  512
#define IMGW   384.0f
#define IMGH   384.0f
#define NMS_T  0.7f
#define MINSZ  16.0f
#define KCHUNKS 16
#define CPART  32
#define VMAX   1024   // static bound: anchor-valid count is 951 for this geometry
#define NWp    16     // VMAX/64
#define PT     1024

typedef unsigned long long u64;

// ---------------- scratch (device globals; zero-initialized) ------------------
__device__ float g_hpart[KCHUNKS * MIDCH * NPIX];

__device__ float g_x0[NN], g_y0[NN], g_ws[NN], g_hs[NN], g_prob[NN];
__device__ u64 g_ckeys[NN];          // compacted valid keys (low 32 = orig idx)
__device__ int g_vcount;

// ---------------- 1. conv 3x3, 512->24, partial over K chunks -----------------
__global__ void conv_part_kernel(const float* __restrict__ x,
                                 const float* __restrict__ W) {
    const int y  = blockIdx.x;
    const int kc = blockIdx.y;
    const int c0 = kc * CPART;

    if (y == 0 && kc == 0 && threadIdx.x == 0) g_vcount = 0;  // reset per replay

    __shared__ float xs[CPART][3][26];
    __shared__ float ws[MIDCH][CPART][9];

    const int tid = threadIdx.x;        // 576

    for (int idx = tid; idx < CPART * 3 * 26; idx += 576) {
        int c  = idx / 78;
        int r  = (idx % 78) / 26;
        int xx = idx % 26;
        int gy = y + r - 1;
        int gx = xx - 1;
        float v = 0.0f;
        if (gy >= 0 && gy < FEAT && gx >= 0 && gx < FEAT)
            v = x[(c0 + c) * NPIX + gy * FEAT + gx];
        xs[c][r][xx] = v;
    }
    for (int idx = tid; idx < MIDCH * CPART * 9; idx += 576) {
        int o = idx / (CPART * 9);
        int c = (idx % (CPART * 9)) / 9;
        int t = idx % 9;
        ws[o][c][t] = W[((o * CINCH) + c0 + c) * 9 + t];
    }
    __syncthreads();

    const int xc = tid % FEAT;
    const int o  = tid / FEAT;
    float acc = 0.0f;
    #pragma unroll 4
    for (int c = 0; c < CPART; c++) {
        float a0 = xs[c][0][xc], a1 = xs[c][0][xc+1], a2 = xs[c][0][xc+2];
        float b0 = xs[c][1][xc], b1 = xs[c][1][xc+1], b2 = xs[c][1][xc+2];
        float d0 = xs[c][2][xc], d1 = xs[c][2][xc+1], d2 = xs[c][2][xc+2];
        const float* w = ws[o][c];
        acc += a0*w[0] + a1*w[1] + a2*w[2]
             + b0*w[3] + b1*w[4] + b2*w[5]
             + d0*w[6] + d1*w[7] + d2*w[8];
    }
    g_hpart[kc * (MIDCH*NPIX) + o * NPIX + y * FEAT + xc] = acc;
}

// ---------------- 2. heads + decode + valid compaction + default outputs ------
__global__ __launch_bounds__(288) void decode_kernel(
        const float* __restrict__ Wc, const float* __restrict__ bc,
        const float* __restrict__ Wr, const float* __restrict__ br,
        const float* __restrict__ brpn,
        const float* __restrict__ anchors,
        float* __restrict__ out) {
    __shared__ float sh[32][MIDCH];
    __shared__ float sWc[2*KANCH*MIDCH];
    __shared__ float sWr[4*KANCH*MIDCH];
    __shared__ float sbc[2*KANCH];
    __shared__ float sbr[4*KANCH];

    const int tid = threadIdx.x;
    const int p0  = blockIdx.x * 32;

    for (int i = tid; i < 32 * MIDCH; i += 288) {
        int ch = i / 32, pp = i % 32;
        float s = 0.0f;
        #pragma unroll
        for (int kc = 0; kc < KCHUNKS; kc++)
            s += g_hpart[kc * (MIDCH*NPIX) + ch * NPIX + p0 + pp];
        sh[pp][ch] = fmaxf(s + brpn[ch], 0.0f);
    }
    for (int i = tid; i < 2*KANCH*MIDCH; i += 288) sWc[i] = Wc[i];
    for (int i = tid; i < 4*KANCH*MIDCH; i += 288) sWr[i] = Wr[i];
    if (tid < 2*KANCH) sbc[tid] = bc[tid];
    if (tid < 4*KANCH) sbr[tid] = br[tid];
    __syncthreads();

    const int lp = tid / KANCH;
    const int k  = tid % KANCH;
    const int n  = (p0 + lp) * KANCH + k;

    float hv[MIDCH];
    #pragma unroll
    for (int o = 0; o < MIDCH; o++) hv[o] = sh[lp][o];

    float c0 = 0.0f, c1 = 0.0f;
    #pragma unroll
    for (int o = 0; o < MIDCH; o++) {
        c0 += hv[o] * sWc[(2*k)   * MIDCH + o];
        c1 += hv[o] * sWc[(2*k+1) * MIDCH + o];
    }
    c0 += sbc[2*k]; c1 += sbc[2*k+1];

    float tx = 0.0f, ty = 0.0f, tw = 0.0f, th = 0.0f;
    #pragma unroll
    for (int o = 0; o < MIDCH; o++) {
        float h = hv[o];
        tx += h * sWr[(4*k)   * MIDCH + o];
        ty += h * sWr[(4*k+1) * MIDCH + o];
        tw += h * sWr[(4*k+2) * MIDCH + o];
        th += h * sWr[(4*k+3) * MIDCH + o];
    }
    tx += sbr[4*k]; ty += sbr[4*k+1]; tw += sbr[4*k+2]; th += sbr[4*k+3];

    out[4*NN + 2*n]     = c0;
    out[4*NN + 2*n + 1] = c1;
    float prob = 1.0f / (1.0f + expf(c0 - c1));

    float ax = anchors[4*n],   ay = anchors[4*n+1];
    float aw = anchors[4*n+2], ah = anchors[4*n+3];

    float px = ax + aw * tx;
    float py = ay + ah * ty;
    float pw = aw * expf(tw);
    float ph = ah * expf(th);
    out[4*n]   = px; out[4*n+1] = py;
    out[4*n+2] = pw; out[4*n+3] = ph;

    float x0 = px - 0.5f * (pw - 1.0f);
    float y0 = py - 0.5f * (ph - 1.0f);
    float x1 = pw + x0 - 1.0f;
    float y1 = ph + y0 - 1.0f;
    x0 = fminf(fmaxf(x0, 0.0f), IMGW - 1.0f);
    x1 = fminf(fmaxf(x1, 0.0f), IMGW - 1.0f);
    y0 = fminf(fmaxf(y0, 0.0f), IMGH - 1.0f);
    y1 = fminf(fmaxf(y1, 0.0f), IMGH - 1.0f);
    float wsv = x1 - x0 + 1.0f;
    float hsv = y1 - y0 + 1.0f;

    float ax0 = ax - 0.5f * (aw - 1.0f);
    float ay0 = ay - 0.5f * (ah - 1.0f);
    float ax1 = aw + ax0 - 1.0f;
    float ay1 = ah + ay0 - 1.0f;
    bool anchor_valid = (ax0 >= 0.0f) && (ay0 >= 0.0f) && (ax1 < IMGW) && (ay1 < IMGH);
    bool valid = anchor_valid && (wsv >= MINSZ) && (hsv >= MINSZ);

    g_x0[n] = x0; g_y0[n] = y0;
    g_ws[n] = wsv; g_hs[n] = hsv; g_prob[n] = prob;

    // default (not-kept) outputs; post overwrites only kept rows
    out[6*NN + 4*n]     = 0.0f;
    out[6*NN + 4*n + 1] = 0.0f;
    out[6*NN + 4*n + 2] = 0.0f;
    out[6*NN + 4*n + 3] = 0.0f;
    out[10*NN + n] = 0.0f;
    out[11*NN + n] = 0.0f;
    out[12*NN + n] = 0.0f;

    if (valid) {
        float f = -prob;
        unsigned u = __float_as_uint(f);
        u = (u & 0x80000000u) ? ~u : (u | 0x80000000u);
        int pos = atomicAdd(&g_vcount, 1);
        g_ckeys[pos] = ((u64)u << 32) | (unsigned)n;
    }
}

// ---------------- 3. fused rank-sort + mask + NMS + finalize (one block) ------
// All state in shared memory. V <= 951 (anchor geometry) <= VMAX.
// Dynamic smem layout:
//   u64   skeys[VMAX]              8 KB
//   u64   smask[VMAX*NWp]        131 KB   (row-major; only words w >= i>>6 written/read)
//   float sx0,sy0,sx1,sy1,sar     20 KB
//   int   sord[VMAX]               4 KB
#define POST_SMEM ((VMAX + VMAX*NWp) * 8 + VMAX * 5 * 4 + VMAX * 4)
__global__ __launch_bounds__(PT) void post_kernel(
        const int* __restrict__ labels, float* __restrict__ out) {
    extern __shared__ char dsm[];
    u64*   skeys = (u64*)dsm;
    u64*   smask = skeys + VMAX;
    float* sx0   = (float*)(smask + VMAX * NWp);
    float* sy0   = sx0 + VMAX;
    float* sx1   = sy0 + VMAX;
    float* sy1   = sx1 + VMAX;
    float* sar   = sy1 + VMAX;
    int*   sord  = (int*)(sar + VMAX);

    __shared__ u64 remv[NWp], vword[NWp], skw[NWp];
    __shared__ int klist[64];
    __shared__ int kn;

    const int tid = threadIdx.x;
    const int V   = g_vcount;            // <= 951
    const int NW  = (V + 63) >> 6;

    for (int i = tid; i < V; i += PT) skeys[i] = g_ckeys[i];
    if (tid < NWp) {
        u64 v = 0ull;
        if ((tid + 1) * 64 <= V) v = ~0ull;
        else if (tid * 64 < V)   v = ((u64)1 << (V - tid * 64)) - 1ull;
        vword[tid] = v;
        remv[tid]  = 0ull;
        skw[tid]   = 0ull;
    }
    __syncthreads();

    // ---- rank + scatter (keys unique -> exact stable argsort permutation) ----
    if (tid < V) {
        const u64 key = skeys[tid];
        int r = 0;
        for (int j = 0; j < V; j++) r += (skeys[j] < key) ? 1 : 0;
        const int n = (int)(unsigned)(key & 0xFFFFFFFFull);
        sord[r] = n;
        float x0 = g_x0[n], y0 = g_y0[n], wv = g_ws[n], hv = g_hs[n];
        sx0[r] = x0;
        sy0[r] = y0;
        sx1[r] = x0 + wv - 1.0f;
        sy1[r] = y0 + hv - 1.0f;
        sar[r] = wv * hv;
    }
    __syncthreads();

    // ---- suppression bitmask: task = (row i, word w), upper-tri words only ----
    {
        const int total = V * NW;
        for (int tsk = tid; tsk < total; tsk += PT) {
            const int i = tsk / NW;
            const int w = tsk % NW;
            if (w < (i >> 6)) continue;           // never read
            const float x0 = sx0[i], y0 = sy0[i], x1 = sx1[i], y1 = sy1[i];
            const float ar = sar[i];
            const int jb = w * 64;
            const int je = min(jb + 64, V);
            u64 m = 0ull;
            for (int j = max(jb, i + 1); j < je; j++) {
                float iw = fminf(x1, sx1[j]) - fmaxf(x0, sx0[j]) + 1.0f;
                float ih = fminf(y1, sy1[j]) - fmaxf(y0, sy0[j]) + 1.0f;
                iw = fmaxf(iw, 0.0f);
                ih = fmaxf(ih, 0.0f);
                float inter = iw * ih;
                float iou = inter / (ar + sar[j] - inter);
                if (iou > NMS_T) m |= (1ull << (j - jb));
            }
            smask[i * NWp + w] = m;
        }
    }
    __syncthreads();

    // ---- greedy NMS over 64-row chunks, all in smem ----
    for (int c = 0; c < NW; c++) {
        if (tid == 0) {
            u64 avail = vword[c] & ~remv[c];
            u64 keep = 0ull;
            int n = 0;
            while (avail) {
                int b = __ffsll((long long)avail) - 1;
                keep |= (1ull << b);
                klist[n++] = b;
                avail &= ~(smask[(size_t)(c * 64 + b) * NWp + c] | (1ull << b));
            }
            skw[c] = keep;
            kn = n;
        }
        __syncthreads();
        const int n = kn;
        if (n > 0 && tid >= 1 && tid <= NW - 1 - c) {
            const int w = c + tid;
            u64 acc = 0ull;
            for (int q = 0; q < n; q++)
                acc |= smask[(size_t)(c * 64 + klist[q]) * NWp + w];
            remv[w] |= acc;
        }
        __syncthreads();
    }

    // ---- finalize kept rows (defaults already written by decode) ----
    for (int i = tid; i < V; i += PT) {
        if ((skw[i >> 6] >> (i & 63)) & 1ull) {
            const int n = sord[i];
            float x0 = g_x0[n], y0 = g_y0[n];
            float wsv = g_ws[n], hsv = g_hs[n];
            out[6*NN + 4*n]     = x0 + 0.5f * (wsv - 1.0f);
            out[6*NN + 4*n + 1] = y0 + 0.5f * (hsv - 1.0f);
            out[6*NN + 4*n + 2] = wsv;
            out[6*NN + 4*n + 3] = hsv;
            out[10*NN + n] = g_prob[n];
            out[11*NN + n] = (float)labels[n];
            out[12*NN + n] = 1.0f;
        }
    }
}

// -------------------------------------------------------------------------------
extern "C" void kernel_launch(void* const* d_in, const int* in_sizes, int n_in,
                              void* d_out, int out_size) {
    const float* x       = (const float*)d_in[0];
    const int*   labels  = (const int*)  d_in[1];
    const float* Wrpn    = (const float*)d_in[2];
    const float* brpn    = (const float*)d_in[3];
    const float* Wc      = (const float*)d_in[4];
    const float* bc      = (const float*)d_in[5];
    const float* Wr      = (const float*)d_in[6];
    const float* br      = (const float*)d_in[7];
    const float* anchors = (const float*)d_in[8];
    float* out = (float*)d_out;

    cudaFuncSetAttribute(post_kernel,
                         cudaFuncAttributeMaxDynamicSharedMemorySize, POST_SMEM);

    conv_part_kernel<<<dim3(FEAT, KCHUNKS), 576>>>(x, Wrpn);
    decode_kernel<<<NPIX / 32, 288>>>(Wc, bc, Wr, br, brpn, anchors, out);
    post_kernel<<<1, PT, POST_SMEM>>>(labels, out);
}

// round 12
// speedup vs baseline: 4.7904x; 4.7904x over previous
#include <cuda_runtime.h>
#include <cuda_bf16.h>

#define FEAT   24
#define NPIX   (FEAT*FEAT)        // 576
#define KANCH  9
#define NN     (NPIX*KANCH)       // 5184
#define MIDCH  24
#define CINCH  512
#define NWORD  81
#define IMGW   384.0f
#define IMGH   384.0f
#define NMS_T  0.7f
#define MINSZ  16.0f
#define KCHUNKS 16
#define CPART  32
#define TPW    6
#define MBLK   22   // static tile-grid bound: covers V <= 1408 (anchor-valid max ~951)

typedef unsigned long long u64;

// ---------------- scratch (device globals; zero-initialized) ------------------
__device__ float g_hpart[KCHUNKS * MIDCH * NPIX];

__device__ float g_x0[NN], g_y0[NN], g_ws[NN], g_hs[NN], g_prob[NN];
__device__ u64 g_ckeys[NN];          // compacted valid keys (low 32 = orig idx)
__device__ int g_vcount;

__device__ float g_bx0[NN], g_by0[NN], g_bx1[NN], g_by1[NN], g_barea[NN];
__device__ int g_order[NN];          // sorted pos -> original index

__device__ u64 g_mask[NN * NWORD];

// ---------------- 1. conv 3x3, 512->24 — register-tiled (4 px x 4 rows) -------
// grid (6, 16): blockIdx.x = row group (4 rows), blockIdx.y = K chunk.
// 576 threads = 24 o x 6 xgroups(4 px) x 4 rows. 0.75 LDS per MAC.
__global__ __launch_bounds__(576) void conv_part_kernel(
        const float* __restrict__ x, const float* __restrict__ W) {
    const int y0 = blockIdx.x * 4;
    const int kc = blockIdx.y;
    const int c0 = kc * CPART;

    if (blockIdx.x == 0 && kc == 0 && threadIdx.x == 0) g_vcount = 0;

    __shared__ float xs[CPART][6][26];          // rows y0-1 .. y0+4, padded cols
    __shared__ float ws[MIDCH][CPART][9];

    const int tid = threadIdx.x;        // 576

    for (int idx = tid; idx < CPART * 6 * 26; idx += 576) {
        int c  = idx / 156;
        int r  = (idx % 156) / 26;
        int xx = idx % 26;
        int gy = y0 + r - 1;
        int gx = xx - 1;
        float v = 0.0f;
        if (gy >= 0 && gy < FEAT && gx >= 0 && gx < FEAT)
            v = x[(c0 + c) * NPIX + gy * FEAT + gx];
        xs[c][r][xx] = v;
    }
    for (int idx = tid; idx < MIDCH * CPART * 9; idx += 576) {
        int o = idx / (CPART * 9);
        int c = (idx % (CPART * 9)) / 9;
        int t = idx % 9;
        ws[o][c][t] = W[((o * CINCH) + c0 + c) * 9 + t];
    }
    __syncthreads();

    const int o   = tid / 24;           // 0..23
    const int rem = tid % 24;
    const int xg  = rem / 4;            // 0..5
    const int yl  = rem % 4;            // 0..3
    const int xc0 = xg * 4;

    float a0 = 0.0f, a1 = 0.0f, a2 = 0.0f, a3 = 0.0f;

    #pragma unroll 2
    for (int c = 0; c < CPART; c++) {
        const float* w = ws[o][c];
        float w0 = w[0], w1 = w[1], w2 = w[2];
        float w3 = w[3], w4 = w[4], w5 = w[5];
        float w6 = w[6], w7 = w[7], w8 = w[8];

        const float* r0 = &xs[c][yl][xc0];
        const float* r1 = &xs[c][yl+1][xc0];
        const float* r2 = &xs[c][yl+2][xc0];
        float u0 = r0[0], u1 = r0[1], u2 = r0[2], u3 = r0[3], u4 = r0[4], u5 = r0[5];
        float v0 = r1[0], v1 = r1[1], v2 = r1[2], v3 = r1[3], v4 = r1[4], v5 = r1[5];
        float z0 = r2[0], z1 = r2[1], z2 = r2[2], z3 = r2[3], z4 = r2[4], z5 = r2[5];

        a0 += u0*w0 + u1*w1 + u2*w2 + v0*w3 + v1*w4 + v2*w5 + z0*w6 + z1*w7 + z2*w8;
        a1 += u1*w0 + u2*w1 + u3*w2 + v1*w3 + v2*w4 + v3*w5 + z1*w6 + z2*w7 + z3*w8;
        a2 += u2*w0 + u3*w1 + u4*w2 + v2*w3 + v3*w4 + v4*w5 + z2*w6 + z3*w7 + z4*w8;
        a3 += u3*w0 + u4*w1 + u5*w2 + v3*w3 + v4*w4 + v5*w5 + z3*w6 + z4*w7 + z5*w8;
    }

    float* dst = &g_hpart[kc * (MIDCH*NPIX) + o * NPIX + (y0 + yl) * FEAT + xc0];
    dst[0] = a0; dst[1] = a1; dst[2] = a2; dst[3] = a3;
}

// ---------------- 2. heads + decode + valid compaction + default outputs ------
__global__ __launch_bounds__(288) void decode_kernel(
        const float* __restrict__ Wc, const float* __restrict__ bc,
        const float* __restrict__ Wr, const float* __restrict__ br,
        const float* __restrict__ brpn,
        const float* __restrict__ anchors,
        float* __restrict__ out) {
    __shared__ float sh[32][MIDCH];
    __shared__ float sWc[2*KANCH*MIDCH];
    __shared__ float sWr[4*KANCH*MIDCH];
    __shared__ float sbc[2*KANCH];
    __shared__ float sbr[4*KANCH];

    const int tid = threadIdx.x;
    const int p0  = blockIdx.x * 32;

    for (int i = tid; i < 32 * MIDCH; i += 288) {
        int ch = i / 32, pp = i % 32;
        float s = 0.0f;
        #pragma unroll
        for (int kc = 0; kc < KCHUNKS; kc++)
            s += g_hpart[kc * (MIDCH*NPIX) + ch * NPIX + p0 + pp];
        sh[pp][ch] = fmaxf(s + brpn[ch], 0.0f);
    }
    for (int i = tid; i < 2*KANCH*MIDCH; i += 288) sWc[i] = Wc[i];
    for (int i = tid; i < 4*KANCH*MIDCH; i += 288) sWr[i] = Wr[i];
    if (tid < 2*KANCH) sbc[tid] = bc[tid];
    if (tid < 4*KANCH) sbr[tid] = br[tid];
    __syncthreads();

    const int lp = tid / KANCH;
    const int k  = tid % KANCH;
    const int n  = (p0 + lp) * KANCH + k;

    float hv[MIDCH];
    #pragma unroll
    for (int o = 0; o < MIDCH; o++) hv[o] = sh[lp][o];

    float c0 = 0.0f, c1 = 0.0f;
    #pragma unroll
    for (int o = 0; o < MIDCH; o++) {
        c0 += hv[o] * sWc[(2*k)   * MIDCH + o];
        c1 += hv[o] * sWc[(2*k+1) * MIDCH + o];
    }
    c0 += sbc[2*k]; c1 += sbc[2*k+1];

    float tx = 0.0f, ty = 0.0f, tw = 0.0f, th = 0.0f;
    #pragma unroll
    for (int o = 0; o < MIDCH; o++) {
        float h = hv[o];
        tx += h * sWr[(4*k)   * MIDCH + o];
        ty += h * sWr[(4*k+1) * MIDCH + o];
        tw += h * sWr[(4*k+2) * MIDCH + o];
        th += h * sWr[(4*k+3) * MIDCH + o];
    }
    tx += sbr[4*k]; ty += sbr[4*k+1]; tw += sbr[4*k+2]; th += sbr[4*k+3];

    out[4*NN + 2*n]     = c0;
    out[4*NN + 2*n + 1] = c1;
    float prob = 1.0f / (1.0f + expf(c0 - c1));

    float ax = anchors[4*n],   ay = anchors[4*n+1];
    float aw = anchors[4*n+2], ah = anchors[4*n+3];

    float px = ax + aw * tx;
    float py = ay + ah * ty;
    float pw = aw * expf(tw);
    float ph = ah * expf(th);
    out[4*n]   = px; out[4*n+1] = py;
    out[4*n+2] = pw; out[4*n+3] = ph;

    float x0 = px - 0.5f * (pw - 1.0f);
    float y0 = py - 0.5f * (ph - 1.0f);
    float x1 = pw + x0 - 1.0f;
    float y1 = ph + y0 - 1.0f;
    x0 = fminf(fmaxf(x0, 0.0f), IMGW - 1.0f);
    x1 = fminf(fmaxf(x1, 0.0f), IMGW - 1.0f);
    y0 = fminf(fmaxf(y0, 0.0f), IMGH - 1.0f);
    y1 = fminf(fmaxf(y1, 0.0f), IMGH - 1.0f);
    float wsv = x1 - x0 + 1.0f;
    float hsv = y1 - y0 + 1.0f;

    float ax0 = ax - 0.5f * (aw - 1.0f);
    float ay0 = ay - 0.5f * (ah - 1.0f);
    float ax1 = aw + ax0 - 1.0f;
    float ay1 = ah + ay0 - 1.0f;
    bool anchor_valid = (ax0 >= 0.0f) && (ay0 >= 0.0f) && (ax1 < IMGW) && (ay1 < IMGH);
    bool valid = anchor_valid && (wsv >= MINSZ) && (hsv >= MINSZ);

    g_x0[n] = x0; g_y0[n] = y0;
    g_ws[n] = wsv; g_hs[n] = hsv; g_prob[n] = prob;

    // default (not-kept) outputs; NMS overwrites only kept rows
    out[6*NN + 4*n]     = 0.0f;
    out[6*NN + 4*n + 1] = 0.0f;
    out[6*NN + 4*n + 2] = 0.0f;
    out[6*NN + 4*n + 3] = 0.0f;
    out[10*NN + n] = 0.0f;
    out[11*NN + n] = 0.0f;
    out[12*NN + n] = 0.0f;

    if (valid) {
        float f = -prob;
        unsigned u = __float_as_uint(f);
        u = (u & 0x80000000u) ? ~u : (u | 0x80000000u);
        int pos = atomicAdd(&g_vcount, 1);
        g_ckeys[pos] = ((u64)u << 32) | (unsigned)n;
    }
}

// ---------------- 3. fused rank-sort + scatter over valid subset --------------
__global__ __launch_bounds__(288) void ranksort_kernel() {
    __shared__ u64 sk[NN];               // 41.5 KB
    const int V = g_vcount;
    if (blockIdx.x * 288 >= V) return;

    const int tid = threadIdx.x;
    for (int j = tid; j < V; j += 288) sk[j] = g_ckeys[j];
    __syncthreads();

    const int i = blockIdx.x * 288 + tid;
    if (i >= V) return;

    const u64 key = sk[i];
    int r = 0;
    #pragma unroll 4
    for (int j = 0; j < V; j++) r += (sk[j] < key) ? 1 : 0;

    const int n = (int)(unsigned)(key & 0xFFFFFFFFull);
    g_order[r]  = n;
    float x0 = g_x0[n], y0 = g_y0[n], wsv = g_ws[n], hsv = g_hs[n];
    g_bx0[r]   = x0;
    g_by0[r]   = y0;
    g_bx1[r]   = x0 + wsv - 1.0f;
    g_by1[r]   = y0 + hsv - 1.0f;
    g_barea[r] = wsv * hsv;
}

// ---------------- 4. suppression bitmask (static 22x22 tile grid) --------------
__global__ void mask_kernel() {
    const int rb = blockIdx.y, cb = blockIdx.x;
    if (cb < rb) return;
    const int V = g_vcount;
    if (rb * 64 >= V || cb * 64 >= V) return;

    const int t = threadIdx.x;           // 64
    const int i = rb * 64 + t;

    __shared__ float cx0[64], cy0[64], cx1[64], cy1[64], car[64];
    {
        int j = cb * 64 + t;
        cx0[t] = g_bx0[j]; cy0[t] = g_by0[j];
        cx1[t] = g_bx1[j]; cy1[t] = g_by1[j];
        car[t] = g_barea[j];
    }
    __syncthreads();

    u64 w = 0ull;
    if (i < V) {
        float x0 = g_bx0[i], y0 = g_by0[i], x1 = g_bx1[i], y1 = g_by1[i];
        float ar = g_barea[i];
        int jbase = cb * 64;
        #pragma unroll 8
        for (int b = 0; b < 64; b++) {
            int j = jbase + b;
            if (j > i) {
                float iw = fminf(x1, cx1[b]) - fmaxf(x0, cx0[b]) + 1.0f;
                float ih = fminf(y1, cy1[b]) - fmaxf(y0, cy0[b]) + 1.0f;
                iw = fmaxf(iw, 0.0f);
                ih = fmaxf(ih, 0.0f);
                float inter = iw * ih;
                float iou = inter / (ar + car[b] - inter);
                if (iou > NMS_T) w |= (1ull << b);
            }
        }
    }
    g_mask[(size_t)i * NWORD + cb] = w;
}

// ---------------- 5. pipelined greedy NMS + kept-row finalize ------------------
#define RT 640
__global__ __launch_bounds__(RT) void nms_kernel(
        const int* __restrict__ labels, float* __restrict__ out) {
    __shared__ u64 sblk[2][128][4];
    __shared__ u64 part[NWORD][TPW];
    __shared__ u64 remv_s[NWORD + 3];
    __shared__ u64 vword[NWORD + 1];
    __shared__ u64 skw[NWORD + 1];
    __shared__ int kb[2][128];
    __shared__ int kcnt[2];

    const int tid = threadIdx.x;
    const int V   = g_vcount;
    const int NWORDv = (V + 63) >> 6;
    const int NCHv   = (V + 127) >> 7;

    for (int i = tid; i < NWORD * TPW; i += RT) ((u64*)part)[i] = 0ull;
    for (int w = tid; w < NWORD + 3; w += RT) remv_s[w] = 0ull;
    for (int w = tid; w < NWORD + 1; w += RT) {
        u64 v = 0ull;
        if ((w + 1) * 64 <= V) v = ~0ull;
        else if (w * 64 < V)   v = ((u64)1 << (V - w * 64)) - 1ull;
        vword[w] = v;
        skw[w] = 0ull;
    }
    if (tid == 0) { kcnt[0] = 0; kcnt[1] = 0; }

    for (int e = tid; e < 512; e += RT) {        // prefetch chunk 0
        int r = e >> 2, wq = e & 3;
        sblk[0][r][wq] = g_mask[(size_t)r * NWORD + wq];
    }
    __syncthreads();

    for (int t = 0; t < NCHv; t++) {
        const int p = t & 1;

        if (tid == 0) {
            u64 p0 = part[2*t][0] | part[2*t][1] | part[2*t][2]
                   | part[2*t][3] | part[2*t][4] | part[2*t][5];
            u64 p1 = part[2*t+1][0] | part[2*t+1][1] | part[2*t+1][2]
                   | part[2*t+1][3] | part[2*t+1][4] | part[2*t+1][5];
            u64 avail0 = vword[2*t]   & ~(remv_s[2*t]   | p0);
            u64 avail1 = vword[2*t+1] & ~(remv_s[2*t+1] | p1);
            u64 k0 = 0ull, k1 = 0ull, r2 = 0ull, r3 = 0ull;
            int n = 0;
            while (avail0 | avail1) {
                int b;
                if (avail0) {
                    b = __ffsll((long long)avail0) - 1;
                    k0 |= (1ull << b);
                    avail0 &= ~(1ull << b);
                } else {
                    int bb = __ffsll((long long)avail1) - 1;
                    b = 64 + bb;
                    k1 |= (1ull << bb);
                    avail1 &= ~(1ull << bb);
                }
                const u64* dd = sblk[p][b];
                avail0 &= ~dd[0];
                avail1 &= ~dd[1];
                r2 |= dd[2];
                r3 |= dd[3];
                kb[p][n++] = b;
            }
            kcnt[p] = n;
            skw[2*t]   = k0;
            skw[2*t+1] = k1;
            remv_s[2*t+2] |= r2;
            remv_s[2*t+3] |= r3;
        } else if (tid >= 32 && tid < 32 + 80 * TPW) {
            if (t > 0) {
                const int np = kcnt[p ^ 1];
                if (np > 0) {
                    int wi  = (tid - 32) / TPW;
                    int sub = (tid - 32) % TPW;
                    int w   = 2*t + 2 + wi;
                    if (w < NWORDv && vword[w]) {
                        const int bRp  = (t - 1) * 128;
                        const int* kbp = kb[p ^ 1];
                        u64 acc = 0ull;
                        for (int q = sub; q < np; q += TPW)
                            acc |= g_mask[(size_t)(bRp + kbp[q]) * NWORD + w];
                        if (acc) part[w][sub] |= acc;
                    }
                }
            }
        } else if (tid >= 512) {
            const int tt = t + 1;
            if (tt < NCHv) {
                const int bR2 = tt * 128;
                for (int e = tid - 512; e < 512; e += RT - 512) {
                    int r = e >> 2, wq = e & 3;
                    int row = bR2 + r;
                    int gw  = 2*tt + wq;
                    u64 v = 0ull;
                    if (row < NN && gw < NWORD)
                        v = g_mask[(size_t)row * NWORD + gw];
                    sblk[p ^ 1][r][wq] = v;
                }
            }
        }
        __syncthreads();
    }

    // finalize kept rows only (defaults already written by decode)
    for (int i = tid; i < V; i += RT) {
        if ((skw[i >> 6] >> (i & 63)) & 1ull) {
            int n = g_order[i];
            float x0 = g_x0[n], y0 = g_y0[n];
            float wsv = g_ws[n], hsv = g_hs[n];
            out[6*NN + 4*n]     = x0 + 0.5f * (wsv - 1.0f);
            out[6*NN + 4*n + 1] = y0 + 0.5f * (hsv - 1.0f);
            out[6*NN + 4*n + 2] = wsv;
            out[6*NN + 4*n + 3] = hsv;
            out[10*NN + n] = g_prob[n];
            out[11*NN + n] = (float)labels[n];
            out[12*NN + n] = 1.0f;
        }
    }
}

// -------------------------------------------------------------------------------
extern "C" void kernel_launch(void* const* d_in, const int* in_sizes, int n_in,
                              void* d_out, int out_size) {
    const float* x       = (const float*)d_in[0];
    const int*   labels  = (const int*)  d_in[1];
    const float* Wrpn    = (const float*)d_in[2];
    const float* brpn    = (const float*)d_in[3];
    const float* Wc      = (const float*)d_in[4];
    const float* bc      = (const float*)d_in[5];
    const float* Wr      = (const float*)d_in[6];
    const float* br      = (const float*)d_in[7];
    const float* anchors = (const float*)d_in[8];
    float* out = (float*)d_out;

    conv_part_kernel<<<dim3(FEAT/4, KCHUNKS), 576>>>(x, Wrpn);
    decode_kernel<<<NPIX / 32, 288>>>(Wc, bc, Wr, br, brpn, anchors, out);
    ranksort_kernel<<<18, 288>>>();
    mask_kernel<<<dim3(MBLK, MBLK), 64>>>();
    nms_kernel<<<1, RT>>>(labels, out);
}